// round 2
// baseline (speedup 1.0000x reference)
#include <cuda_runtime.h>
#include <cstdint>

#define N_  4
#define C_  128
#define H_  128
#define W_  128
#define OC  8
#define OH  256
#define OW  256

// Per-channel-group partial conv outputs: [cg][n][o][h][w]
__device__ float g_part[4][N_*OC*H_*W_];

// ---- f32x2 helpers (sm_103a packed fp32 pipe; FFMA2 only reachable via PTX) ----
__device__ __forceinline__ unsigned long long pack2(float lo, float hi) {
    unsigned long long r;
    asm("mov.b64 %0, {%1, %2};" : "=l"(r) : "f"(lo), "f"(hi));
    return r;
}
__device__ __forceinline__ void unpack2(unsigned long long v, float& lo, float& hi) {
    asm("mov.b64 {%0, %1}, %2;" : "=f"(lo), "=f"(hi) : "l"(v));
}
__device__ __forceinline__ unsigned long long fma2(unsigned long long a,
                                                   unsigned long long b,
                                                   unsigned long long c) {
    unsigned long long d;
    asm("fma.rn.f32x2 %0, %1, %2, %3;" : "=l"(d) : "l"(a), "l"(b), "l"(c));
    return d;
}

// ---------------------------------------------------------------------------
// Kernel 1: 3x3 SAME conv, 32-channel partial per block.
// Tile 32x32 pixels, 256 threads, each thread computes a 1x4 vertical strip
// of pixels for all 8 output channels (f32x2-packed row pairs).
// Grid: (4, 4, 16) with bz = n*4 + cgroup.
// ---------------------------------------------------------------------------
__global__ __launch_bounds__(256) void conv_part_kernel(
    const float* __restrict__ x,
    const float* __restrict__ wt,    // [o][c][3][3]
    const float* __restrict__ bs)    // [o]
{
    __shared__ float xs[8*34*34];                 // 8 channels, 34x34 halo tile
    __shared__ unsigned long long ws2[8*9*8];     // [cc][tap][o], weight duplicated {w,w}

    const int tid = threadIdx.x;
    const int n  = blockIdx.z >> 2;
    const int cg = blockIdx.z & 3;
    const int h0 = blockIdx.y * 32;
    const int w0 = blockIdx.x * 32;
    const int tx  = tid & 31;
    const int ty0 = (tid >> 5) * 4;

    unsigned long long a01[OC], a23[OC];
    if (cg == 0) {
#pragma unroll
        for (int o = 0; o < OC; o++) {
            float b = __ldg(&bs[o]);
            a01[o] = pack2(b, b);
            a23[o] = a01[o];
        }
    } else {
#pragma unroll
        for (int o = 0; o < OC; o++) { a01[o] = 0ull; a23[o] = 0ull; }
    }

    const float* xn = x + ((size_t)n*C_ + cg*32) * (H_*W_);

    for (int ch = 0; ch < 4; ch++) {
        const int c0 = ch * 8;   // relative to group start
        __syncthreads();
        // Stage chunk weights (duplicated to f32x2)
        for (int i = tid; i < 8*9*8; i += 256) {
            int cc = i / 72;
            int r  = i - cc*72;          // tap*8 + o
            int tap = r >> 3;
            int o   = r & 7;
            float wv = wt[((size_t)o*C_ + (cg*32 + c0 + cc))*9 + tap];
            ws2[i] = pack2(wv, wv);
        }
        // Stage 8 channels of 34x34 halo tile (zero padded)
        for (int i = tid; i < 8*34*34; i += 256) {
            int cc = i / 1156;
            int r  = i - cc*1156;
            int ly = r / 34;
            int lx = r - ly*34;
            int gy = h0 - 1 + ly;
            int gx = w0 - 1 + lx;
            float v = 0.f;
            if ((unsigned)gy < H_ && (unsigned)gx < W_)
                v = xn[(c0+cc)*(H_*W_) + gy*W_ + gx];
            xs[i] = v;
        }
        __syncthreads();

#pragma unroll
        for (int cc = 0; cc < 8; cc++) {
            const float* xb = &xs[cc*1156 + ty0*34 + tx];
#pragma unroll
            for (int kx = 0; kx < 3; kx++) {
                float v[6];
#pragma unroll
                for (int r = 0; r < 6; r++)
                    v[r] = xb[r*34 + kx];
#pragma unroll
                for (int ky = 0; ky < 3; ky++) {
                    unsigned long long p01 = pack2(v[ky],   v[ky+1]);
                    unsigned long long p23 = pack2(v[ky+2], v[ky+3]);
                    const unsigned long long* wp = &ws2[cc*72 + (ky*3 + kx)*8];
#pragma unroll
                    for (int o = 0; o < OC; o++) {
                        unsigned long long w2 = wp[o];
                        a01[o] = fma2(p01, w2, a01[o]);
                        a23[o] = fma2(p23, w2, a23[o]);
                    }
                }
            }
        }
    }

    const int w = w0 + tx;
    float* gp = g_part[cg];
#pragma unroll
    for (int o = 0; o < OC; o++) {
        float r0, r1, r2, r3;
        unpack2(a01[o], r0, r1);
        unpack2(a23[o], r2, r3);
        size_t base = (((size_t)n*OC + o)*H_ + (h0 + ty0))*W_ + w;
        gp[base        ] = r0;
        gp[base +   W_ ] = r1;
        gp[base + 2*W_ ] = r2;
        gp[base + 3*W_ ] = r3;
    }
}

// ---------------------------------------------------------------------------
// Kernel 2: bilinear sampling + pixel shuffle.
// One block per (n, h). 256 threads = 64 w-pairs x 2 kh x 2 channel-phases.
// Each thread: 4 sample points (2 adjacent w, 2 kw), 16 independent LDGs per
// channel, one STG.128 per channel (out cols 4wp..4wp+3).
// ---------------------------------------------------------------------------
__global__ __launch_bounds__(256) void sample_kernel(
    const float* __restrict__ x,
    float* __restrict__ out)
{
    __shared__ float soff[OC][W_];

    const int b = blockIdx.x;
    const int n = b >> 7;
    const int h = b & (H_-1);
    const int tid = threadIdx.x;

    // Stage offsets for this row: sum the 4 conv partials (bias already in cg0)
    for (int i = tid; i < OC*W_; i += 256) {
        int o  = i >> 7;
        int ww = i & (W_-1);
        size_t idx = (((size_t)n*OC + o)*H_ + h)*W_ + ww;
        soff[o][ww] = g_part[0][idx] + g_part[1][idx] + g_part[2][idx] + g_part[3][idx];
    }
    __syncthreads();

    const int wp = tid & 63;
    const int kh = (tid >> 6) & 1;
    const int ci = tid >> 7;

    int   cidx[4][4];
    float cwg[4][4];
#pragma unroll
    for (int p = 0; p < 4; p++) {
        const int wloc = 2*wp + (p >> 1);
        const int kw   = p & 1;
        const int ob   = (kh*2 + kw)*2;
        float sy = (float)h    + soff[ob  ][wloc];
        float sx = (float)wloc + soff[ob+1][wloc];
        float y0f = floorf(sy), x0f = floorf(sx);
        int   y0 = (int)y0f,   x0 = (int)x0f;
        float fy = sy - y0f,   fx = sx - x0f;
        float wc[4];
        wc[0] = (1.f - fy) * (1.f - fx);
        wc[1] = (1.f - fy) * fx;
        wc[2] = fy * (1.f - fx);
        wc[3] = fy * fx;
#pragma unroll
        for (int k = 0; k < 4; k++) {
            int yi = y0 + (k >> 1);
            int xi = x0 + (k & 1);
            bool valid = ((unsigned)yi < H_) && ((unsigned)xi < W_);
            int yc = min(max(yi, 0), H_-1);
            int xc = min(max(xi, 0), W_-1);
            cidx[p][k] = yc*W_ + xc;
            cwg[p][k]  = valid ? wc[k] : 0.f;
        }
    }

    const int oh = 2*h + kh;
    const size_t out_base = ((size_t)n*C_)*OH*OW + (size_t)oh*OW + 4*wp;

    for (int c = ci; c < C_; c += 2) {
        const float* xp = x + ((size_t)n*C_ + c)*(H_*W_);
        float v[16];
#pragma unroll
        for (int p = 0; p < 4; p++)
#pragma unroll
            for (int k = 0; k < 4; k++)
                v[p*4+k] = __ldg(xp + cidx[p][k]);

        float r[4];
#pragma unroll
        for (int p = 0; p < 4; p++) {
            float a = v[p*4+0]*cwg[p][0];
            a = fmaf(v[p*4+1], cwg[p][1], a);
            a = fmaf(v[p*4+2], cwg[p][2], a);
            a = fmaf(v[p*4+3], cwg[p][3], a);
            r[p] = a;
        }
        float4 res = make_float4(r[0], r[1], r[2], r[3]);
        *reinterpret_cast<float4*>(out + out_base + (size_t)c*OH*OW) = res;
    }
}

// ---------------------------------------------------------------------------
extern "C" void kernel_launch(void* const* d_in, const int* in_sizes, int n_in,
                              void* d_out, int out_size)
{
    const float* x  = (const float*)d_in[0];
    const float* wt = (const float*)d_in[1];
    const float* bs = (const float*)d_in[2];
    float* out = (float*)d_out;

    conv_part_kernel<<<dim3(4, 4, 16), 256>>>(x, wt, bs);
    sample_kernel<<<N_*H_, 256>>>(x, out);
}

// round 3
// speedup vs baseline: 1.1076x; 1.1076x over previous
#include <cuda_runtime.h>
#include <cstdint>

#define N_  4
#define C_  128
#define H_  128
#define W_  128
#define OC  8
#define OH  256
#define OW  256
#define HW  (H_*W_)

typedef unsigned long long ull;

// Per-channel-group partial conv outputs: [cg][n][o][h][w]
__device__ float g_part[4][N_*OC*H_*W_];

// ---- f32x2 helpers ----
__device__ __forceinline__ ull pack2(float lo, float hi) {
    ull r;
    asm("mov.b64 %0, {%1, %2};" : "=l"(r) : "f"(lo), "f"(hi));
    return r;
}
__device__ __forceinline__ void unpack2(ull v, float& lo, float& hi) {
    asm("mov.b64 {%0, %1}, %2;" : "=f"(lo), "=f"(hi) : "l"(v));
}
__device__ __forceinline__ ull fma2(ull a, ull b, ull c) {
    ull d;
    asm("fma.rn.f32x2 %0, %1, %2, %3;" : "=l"(d) : "l"(a), "l"(b), "l"(c));
    return d;
}

// ---------------------------------------------------------------------------
// Kernel 1: 3x3 SAME conv, 32-channel partial per block.
// 128 threads, 32x32 pixel tile. Thread = (w-pair tx, 4-row strip ty).
// Each weight LDS feeds 4 FFMA2 = 8 pixels. Grid (4,4,16), bz = n*4+cg.
// ---------------------------------------------------------------------------
__global__ __launch_bounds__(128) void conv_part_kernel(
    const float* __restrict__ x,
    const float* __restrict__ wt,    // [o][c][3][3]
    const float* __restrict__ bs)    // [o]
{
    __shared__ float xs[8][34*34];   // 8 channels, 34x34 halo tile
    __shared__ ull ws2[8][9][8];     // [cc][tap][o] duplicated {w,w}

    const int tid = threadIdx.x;
    const int n  = blockIdx.z >> 2;
    const int cg = blockIdx.z & 3;
    const int h0 = blockIdx.y * 32;
    const int w0 = blockIdx.x * 32;
    const int tx = tid & 15;        // w-pair: covers w0+2tx, w0+2tx+1
    const int ty = tid >> 4;        // 0..7: rows h0+4ty .. h0+4ty+3

    ull acc[OC][4];
    if (cg == 0) {
#pragma unroll
        for (int o = 0; o < OC; o++) {
            float b = __ldg(&bs[o]);
            ull bb = pack2(b, b);
#pragma unroll
            for (int r = 0; r < 4; r++) acc[o][r] = bb;
        }
    } else {
#pragma unroll
        for (int o = 0; o < OC; o++)
#pragma unroll
            for (int r = 0; r < 4; r++) acc[o][r] = 0ull;
    }

    const float* xn = x + ((size_t)n*C_ + cg*32) * HW;

    for (int ch = 0; ch < 4; ch++) {
        const int c0 = ch * 8;
        __syncthreads();
        // Stage weights (duplicated f32x2)
        for (int i = tid; i < 8*9*8; i += 128) {
            int cc  = i / 72;
            int r   = i - cc*72;
            int tap = r >> 3;
            int o   = r & 7;
            float wv = wt[((size_t)o*C_ + (cg*32 + c0 + cc))*9 + tap];
            ws2[cc][tap][o] = pack2(wv, wv);
        }
        // Stage 8 channels of 34x34 halo tile (zero padded)
#pragma unroll
        for (int cc = 0; cc < 8; cc++) {
            const float* xc = xn + (c0+cc)*HW;
            for (int i = tid; i < 34*34; i += 128) {
                int ly = i / 34;
                int lx = i - ly*34;
                int gy = h0 - 1 + ly;
                int gx = w0 - 1 + lx;
                float v = 0.f;
                if ((unsigned)gy < H_ && (unsigned)gx < W_)
                    v = xc[gy*W_ + gx];
                xs[cc][i] = v;
            }
        }
        __syncthreads();

#pragma unroll
        for (int cc = 0; cc < 8; cc++) {
            // base: halo coords of pixel (h0+4ty, w0+2tx) tap origin
            const float* xb = &xs[cc][(4*ty)*34 + 2*tx];
#pragma unroll
            for (int kx = 0; kx < 3; kx++) {
                ull pr[6];
#pragma unroll
                for (int s = 0; s < 6; s++) {
                    float a = xb[s*34 + kx];
                    float b = xb[s*34 + kx + 1];
                    pr[s] = pack2(a, b);
                }
#pragma unroll
                for (int ky = 0; ky < 3; ky++) {
                    const ull* wp = &ws2[cc][ky*3 + kx][0];
#pragma unroll
                    for (int o = 0; o < OC; o++) {
                        ull w2 = wp[o];
                        acc[o][0] = fma2(pr[ky+0], w2, acc[o][0]);
                        acc[o][1] = fma2(pr[ky+1], w2, acc[o][1]);
                        acc[o][2] = fma2(pr[ky+2], w2, acc[o][2]);
                        acc[o][3] = fma2(pr[ky+3], w2, acc[o][3]);
                    }
                }
            }
        }
    }

    float* gp = g_part[cg];
#pragma unroll
    for (int o = 0; o < OC; o++) {
#pragma unroll
        for (int r = 0; r < 4; r++) {
            float v0, v1;
            unpack2(acc[o][r], v0, v1);
            size_t base = (((size_t)n*OC + o)*H_ + (h0 + 4*ty + r))*W_ + (w0 + 2*tx);
            *reinterpret_cast<float2*>(&gp[base]) = make_float2(v0, v1);
        }
    }
}

// ---------------------------------------------------------------------------
// Kernel 2: bilinear sampling + pixel shuffle.
// One block per (n, h, kh): 256 threads, tid = w*2 + kw (one point/thread).
// Per channel: 4 LDG gathers, FMAs, one scalar store; warp stores are a
// single contiguous 128B line. Channel loop unrolled x2 for MLP 8.
// ---------------------------------------------------------------------------
__global__ __launch_bounds__(256) void sample_kernel(
    const float* __restrict__ x,
    float* __restrict__ out)
{
    __shared__ float soff[4][W_];   // [2*(kw)+d][w] for this kh

    const int b  = blockIdx.x;
    const int kh = b & 1;
    const int h  = (b >> 1) & (H_-1);
    const int n  = b >> 8;
    const int tid = threadIdx.x;

    // Stage offsets for (n, h, kh): sum 4 conv partials
    for (int i = tid; i < 4*W_; i += 256) {
        int j  = i >> 7;             // 0..3 : kw = j>>1, d = j&1
        int ww = i & (W_-1);
        int o  = (kh*2 + (j >> 1))*2 + (j & 1);
        size_t idx = (((size_t)n*OC + o)*H_ + h)*W_ + ww;
        soff[j][ww] = g_part[0][idx] + g_part[1][idx] + g_part[2][idx] + g_part[3][idx];
    }
    __syncthreads();

    const int kw = tid & 1;
    const int w  = tid >> 1;

    float sy = (float)h + soff[kw*2    ][w];
    float sx = (float)w + soff[kw*2 + 1][w];
    float y0f = floorf(sy), x0f = floorf(sx);
    int   y0 = (int)y0f,   x0 = (int)x0f;
    float fy = sy - y0f,   fx = sx - x0f;

    float cw[4];
    cw[0] = (1.f - fy) * (1.f - fx);
    cw[1] = (1.f - fy) * fx;
    cw[2] = fy * (1.f - fx);
    cw[3] = fy * fx;
    int ci[4];
#pragma unroll
    for (int k = 0; k < 4; k++) {
        int yi = y0 + (k >> 1);
        int xi = x0 + (k & 1);
        bool valid = ((unsigned)yi < H_) && ((unsigned)xi < W_);
        int yc = min(max(yi, 0), H_-1);
        int xc = min(max(xi, 0), W_-1);
        ci[k] = yc*W_ + xc;
        if (!valid) cw[k] = 0.f;
    }

    const float* xp = x + (size_t)n*C_*HW;
    float* op = out + ((size_t)n*C_)*OH*OW + (size_t)(2*h + kh)*OW + (2*w + kw);

#pragma unroll 2
    for (int c = 0; c < C_; c++) {
        float v0 = __ldg(xp + ci[0]);
        float v1 = __ldg(xp + ci[1]);
        float v2 = __ldg(xp + ci[2]);
        float v3 = __ldg(xp + ci[3]);
        float r = v0*cw[0];
        r = fmaf(v1, cw[1], r);
        r = fmaf(v2, cw[2], r);
        r = fmaf(v3, cw[3], r);
        *op = r;
        xp += HW;
        op += OH*OW;
    }
}

// ---------------------------------------------------------------------------
extern "C" void kernel_launch(void* const* d_in, const int* in_sizes, int n_in,
                              void* d_out, int out_size)
{
    const float* x  = (const float*)d_in[0];
    const float* wt = (const float*)d_in[1];
    const float* bs = (const float*)d_in[2];
    float* out = (float*)d_out;

    conv_part_kernel<<<dim3(4, 4, 16), 128>>>(x, wt, bs);
    sample_kernel<<<N_*H_*2, 256>>>(x, out);
}